// round 17
// baseline (speedup 1.0000x reference)
#include <cuda_runtime.h>
#include <math.h>
#include <stdint.h>

#define B_    2
#define QLEN  2048
#define HID   2048
#define HQ    16
#define HKV   4
#define DH    128
#define QKVN  (HQ*DH + 2*HKV*DH)   /* 3072 */
#define NTOK  (B_*QLEN)            /* 4096 */

// ---------------- scratch (device globals: allocation-free) ----------------
__device__ float g_qkv  [NTOK * QKVN];
__device__ float g_q    [B_ * HQ  * QLEN * DH];
__device__ float g_k    [B_ * HKV * QLEN * DH];
__device__ float g_v    [B_ * HKV * QLEN * DH];
__device__ float g_attn [NTOK * HQ * DH];
__device__ float g_hidr [NTOK * HID];    // tf32-rounded inputs
__device__ float g_wqkvr[QKVN * HID];
__device__ float g_wor  [HID * HID];

__device__ __forceinline__ float to_tf32(float x) {
    asm("cvt.rna.tf32.f32 %0, %0;" : "+f"(x));
    return x;
}
__device__ __forceinline__ uint32_t smem_u32(const void* p) {
    return (uint32_t)__cvta_generic_to_shared(p);
}
#define CP_ASYNC16(dst, src) \
    asm volatile("cp.async.cg.shared.global [%0], [%1], 16;" :: "r"(dst), "l"(src))
#define CP_COMMIT() asm volatile("cp.async.commit_group;")
#define CP_WAIT(n)  asm volatile("cp.async.wait_group %0;" :: "n"(n))

__device__ __forceinline__ void mma_tf32(float c[4],
    uint32_t a0, uint32_t a1, uint32_t a2, uint32_t a3,
    uint32_t b0, uint32_t b1)
{
    asm volatile(
        "mma.sync.aligned.m16n8k8.row.col.f32.tf32.tf32.f32 "
        "{%0,%1,%2,%3}, {%4,%5,%6,%7}, {%8,%9}, {%0,%1,%2,%3};"
        : "+f"(c[0]), "+f"(c[1]), "+f"(c[2]), "+f"(c[3])
        : "r"(a0), "r"(a1), "r"(a2), "r"(a3), "r"(b0), "r"(b1));
}

// ---------------- tf32 rounding prepass ------------------------------------
__global__ __launch_bounds__(256) void round_tf32_vec(
    const float* __restrict__ src, float* __restrict__ dst, int n4)
{
    int i = blockIdx.x * 256 + threadIdx.x;
    if (i < n4) {
        float4 v = ((const float4*)src)[i];
        v.x = to_tf32(v.x); v.y = to_tf32(v.y);
        v.z = to_tf32(v.z); v.w = to_tf32(v.w);
        ((float4*)dst)[i] = v;
    }
}

// ---------------- TF32 GEMM: C[M,N] = A[M,K] * B[N,K]^T --------------------
// 128x128 tile, BK=32, 3-stage cp.async pipeline, 256 threads, warp tile 64x32.
#define GST 3
#define GEMM_SMEM (GST * 2 * 128 * 32 * 4)
__global__ __launch_bounds__(256) void gemm_tf32(
    const float* __restrict__ A, const float* __restrict__ Bm,
    float* __restrict__ C, int M, int N, int K)
{
    extern __shared__ float sm_[];
    float* As = sm_;
    float* Bs = sm_ + GST * 4096;

    int tid = threadIdx.x;
    int bm = blockIdx.y * 128, bn = blockIdx.x * 128;
    int lane = tid & 31, wid = tid >> 5;
    int wm = (wid >> 2) * 64, wn = (wid & 3) * 32;
    int r = lane >> 2, c = lane & 3;

    int lrow = tid >> 3;
    int lg   = tid & 7;
    const float* ga = A  + (size_t)(bm + lrow) * K + lg * 4;
    const float* gb = Bm + (size_t)(bn + lrow) * K + lg * 4;
    uint32_t soff = (uint32_t)(lrow * 32 + ((lg ^ (lrow & 7)) * 4)) * 4;
    uint32_t sa = smem_u32(As) + soff;
    uint32_t sb = smem_u32(Bs) + soff;

    int a0[4], b0[4];
    #pragma unroll
    for (int i = 0; i < 4; i++) a0[i] = (wm + i*16 + r) * 32 + c;
    #pragma unroll
    for (int j = 0; j < 4; j++) b0[j] = (wn + j*8  + r) * 32 + c;

    float acc[16][4];
    #pragma unroll
    for (int t = 0; t < 16; t++)
        #pragma unroll
        for (int x = 0; x < 4; x++) acc[t][x] = 0.f;

    int T = K >> 5;
    #pragma unroll
    for (int pst = 0; pst < 2; pst++) {
        #pragma unroll
        for (int it = 0; it < 4; it++) {
            CP_ASYNC16(sa + pst*16384u + it*4096u, ga + pst*32 + (size_t)it*32*K);
            CP_ASYNC16(sb + pst*16384u + it*4096u, gb + pst*32 + (size_t)it*32*K);
        }
        CP_COMMIT();
    }

    for (int t = 0; t < T; t++) {
        if (t + 2 < T) {
            int st = (t + 2) % GST;
            int kt = (t + 2) * 32;
            #pragma unroll
            for (int it = 0; it < 4; it++) {
                CP_ASYNC16(sa + st*16384u + it*4096u, ga + kt + (size_t)it*32*K);
                CP_ASYNC16(sb + st*16384u + it*4096u, gb + kt + (size_t)it*32*K);
            }
        }
        CP_COMMIT();
        CP_WAIT(2);
        __syncthreads();

        const float* Sa = As + (t % GST) * 4096;
        const float* Sb = Bs + (t % GST) * 4096;
        #pragma unroll
        for (int s = 0; s < 4; s++) {
            int off0 = ((2*s) ^ r) * 4;
            int off1 = off0 ^ 4;
            uint32_t af[4][4], bf[4][2];
            #pragma unroll
            for (int i = 0; i < 4; i++) {
                af[i][0] = __float_as_uint(Sa[a0[i] + off0]);
                af[i][1] = __float_as_uint(Sa[a0[i] + 256 + off0]);
                af[i][2] = __float_as_uint(Sa[a0[i] + off1]);
                af[i][3] = __float_as_uint(Sa[a0[i] + 256 + off1]);
            }
            #pragma unroll
            for (int j = 0; j < 4; j++) {
                bf[j][0] = __float_as_uint(Sb[b0[j] + off0]);
                bf[j][1] = __float_as_uint(Sb[b0[j] + off1]);
            }
            #pragma unroll
            for (int i = 0; i < 4; i++)
                #pragma unroll
                for (int j = 0; j < 4; j++)
                    mma_tf32(acc[i*4+j], af[i][0],af[i][1],af[i][2],af[i][3],
                             bf[j][0], bf[j][1]);
        }
        __syncthreads();
    }

    #pragma unroll
    for (int i = 0; i < 4; i++) {
        int row0 = bm + wm + i*16 + r;
        #pragma unroll
        for (int j = 0; j < 4; j++) {
            int col = bn + wn + j*8 + c*2;
            float2 v0; v0.x = acc[i*4+j][0]; v0.y = acc[i*4+j][1];
            float2 v1; v1.x = acc[i*4+j][2]; v1.y = acc[i*4+j][3];
            *(float2*)&C[(size_t)row0*N + col]     = v0;
            *(float2*)&C[(size_t)(row0+8)*N + col] = v1;
        }
    }
}

// ---------------- fused RMSNorm + RoPE + scatter (tf32-rounded out) --------
__global__ __launch_bounds__(128) void rmsnorm_rope(
    const int* __restrict__ pos,
    const float* __restrict__ qw, const float* __restrict__ kw)
{
    int token = blockIdx.x;
    int h = blockIdx.y;
    int d = threadIdx.x;
    int b = token / QLEN, q = token % QLEN;

    if (h >= 20) {  // V: copy + round
        int hv = h - 20;
        g_v[(((size_t)b*HKV + hv)*QLEN + q)*DH + d] =
            to_tf32(g_qkv[(size_t)token*QKVN + HQ*DH + HKV*DH + hv*DH + d]);
        return;
    }
    bool isq = (h < 16);
    int off = isq ? h*DH : HQ*DH + (h-16)*DH;
    float x = g_qkv[(size_t)token*QKVN + off + d];

    __shared__ float red[4];
    __shared__ float sx[128];
    float s = x * x;
    #pragma unroll
    for (int o = 16; o; o >>= 1) s += __shfl_xor_sync(0xffffffffu, s, o);
    if ((d & 31) == 0) red[d >> 5] = s;
    __syncthreads();
    float tot = red[0] + red[1] + red[2] + red[3];
    float r = rsqrtf(tot * (1.0f/DH) + 1e-6f);
    const float* w = isq ? qw : kw;
    float xn = x * r * w[d];
    sx[d] = xn;
    __syncthreads();

    float p = (float)pos[token];
    int i = d & 63;
    float invf = exp2f(-((float)i) * (log2f(1.0e6f) / 64.0f));
    float ang = p * invf;
    float cc = cosf(ang), sn = sinf(ang);
    float outv = (d < 64) ? (sx[d]*cc - sx[d+64]*sn)
                          : (sx[d]*cc + sx[d-64]*sn);
    outv = to_tf32(outv);
    if (isq) g_q[(((size_t)b*HQ  + h     )*QLEN + q)*DH + d] = outv;
    else     g_k[(((size_t)b*HKV + (h-16))*QLEN + q)*DH + d] = outv;
}

// ---------------- flash attention: Q tile 128, KV 64x2, tf32 MMA -----------
#define FBM 128
#define FBN 64
#define SSTR 66
#define FLASH_SMEM ((FBM*DH + 4*FBN*DH + FBM*SSTR + 3*FBM) * 4)   /* 231936 */

__global__ __launch_bounds__(256) void flash_attn()
{
    extern __shared__ float sm_[];
    float* sQ  = sm_;                      // 128 x 128 swizzled
    float* sK  = sQ + FBM*DH;              // 2 x 64 x 128 swizzled
    float* sV  = sK + 2*FBN*DH;            // 2 x 64 x 128 swizzled
    float* sS  = sV + 2*FBN*DH;            // 128 x 66
    float* sMx = sS + FBM*SSTR;
    float* sL  = sMx + FBM;
    float* sA  = sL + FBM;

    int tid = threadIdx.x;
    int lane = tid & 31, wid = tid >> 5;
    int qt = (int)(gridDim.x - 1 - blockIdx.x);   // longest-first
    int h = blockIdx.y, b = blockIdx.z;
    int hkv = h >> 2;

    const float* Qg = g_q + (((size_t)b*HQ  + h  )*QLEN + qt*FBM)*DH;
    const float* Kg = g_k + (((size_t)b*HKV + hkv)*QLEN)*DH;
    const float* Vg = g_v + (((size_t)b*HKV + hkv)*QLEN)*DH;

    // cp.async mapping: row0 = tid>>5 in 0..7, +8 per chunk-iter keeps row&7
    int row0 = tid >> 5, g32 = tid & 31;
    uint32_t swz = (uint32_t)((g32 ^ row0) * 4);
    uint32_t dq = smem_u32(sQ) + (uint32_t)(row0*DH)*4 + swz*4;
    uint32_t dk = smem_u32(sK) + (uint32_t)(row0*DH)*4 + swz*4;
    uint32_t dv = smem_u32(sV) + (uint32_t)(row0*DH)*4 + swz*4;
    const float* gq = Qg + row0*DH + g32*4;
    const float* gk = Kg + row0*DH + g32*4;
    const float* gv = Vg + row0*DH + g32*4;

    // prologue: Q (128 rows = 16 iters of 8 rows) + K0/V0, single group
    #pragma unroll
    for (int it = 0; it < 16; it++) CP_ASYNC16(dq + it*4096u, gq + it*1024);
    #pragma unroll
    for (int it = 0; it < 8; it++) {
        CP_ASYNC16(dk + it*4096u, gk + it*1024);
        CP_ASYNC16(dv + it*4096u, gv + it*1024);
    }
    CP_COMMIT();

    if (tid < FBM) { sMx[tid] = -1e30f; sL[tid] = 0.f; }

    int r = lane >> 2, c = lane & 3;
    int wm  = (wid >> 1) * 32;       // warp m rows (both QK and PV): 0..96
    int wnS = (wid & 1) * 32;        // QK n cols (keys): 0/32
    int wnO = (wid & 1) * 64;        // PV n cols (dh): 0/64

    // fragment base offsets (row&7 == r for all fragment rows)
    int qa0[2], kb0[4];
    #pragma unroll
    for (int i = 0; i < 2; i++) qa0[i] = (wm + i*16 + r) * DH + c;
    #pragma unroll
    for (int j = 0; j < 4; j++) kb0[j] = (wnS + j*8 + r) * DH + c;
    int vcol0[8], vcol1[8];
    #pragma unroll
    for (int j = 0; j < 8; j++) {
        int vx = (wnO >> 2) + 2*j + (r >> 2);
        vcol0[j] = ((vx ^ c) * 4) + (r & 3);
        vcol1[j] = ((vx ^ (c + 4)) * 4) + (r & 3);
    }

    float oacc[16][4];
    #pragma unroll
    for (int t = 0; t < 16; t++)
        #pragma unroll
        for (int x = 0; x < 4; x++) oacc[t][x] = 0.f;

    const float scale = 0.08838834764831845f;   // 1/sqrt(128)
    int kbmax = 2*qt + 1;

    for (int kb = 0; kb <= kbmax; kb++) {
        __syncthreads();   // prior PV reads of buffer we refill (also covers init)
        if (kb + 1 <= kbmax) {
            uint32_t stoff = (uint32_t)(((kb + 1) & 1) * FBN * DH) * 4;
            const float* gk1 = gk + (size_t)(kb + 1) * FBN * DH;
            const float* gv1 = gv + (size_t)(kb + 1) * FBN * DH;
            #pragma unroll
            for (int it = 0; it < 8; it++) {
                CP_ASYNC16(dk + stoff + it*4096u, gk1 + it*1024);
                CP_ASYNC16(dv + stoff + it*4096u, gv1 + it*1024);
            }
        }
        CP_COMMIT();
        CP_WAIT(1);
        __syncthreads();

        const float* Kb = sK + (kb & 1) * FBN * DH;
        const float* Vb = sV + (kb & 1) * FBN * DH;

        // ---- S = Q K^T : warp tile 32x32 (2 m-tiles x 4 n-tiles) ----
        float sacc[8][4];
        #pragma unroll
        for (int t = 0; t < 8; t++)
            #pragma unroll
            for (int x = 0; x < 4; x++) sacc[t][x] = 0.f;
        #pragma unroll
        for (int s = 0; s < 16; s++) {
            int off0 = ((2*s) ^ r) * 4;
            int off1 = off0 ^ 4;
            uint32_t af[2][4], bf[4][2];
            #pragma unroll
            for (int i = 0; i < 2; i++) {
                af[i][0] = __float_as_uint(sQ[qa0[i] + off0]);
                af[i][1] = __float_as_uint(sQ[qa0[i] + 8*DH + off0]);
                af[i][2] = __float_as_uint(sQ[qa0[i] + off1]);
                af[i][3] = __float_as_uint(sQ[qa0[i] + 8*DH + off1]);
            }
            #pragma unroll
            for (int j = 0; j < 4; j++) {
                bf[j][0] = __float_as_uint(Kb[kb0[j] + off0]);
                bf[j][1] = __float_as_uint(Kb[kb0[j] + off1]);
            }
            #pragma unroll
            for (int i = 0; i < 2; i++)
                #pragma unroll
                for (int j = 0; j < 4; j++)
                    mma_tf32(sacc[i*4+j], af[i][0],af[i][1],af[i][2],af[i][3],
                             bf[j][0], bf[j][1]);
        }
        // mask + scale -> sS
        #pragma unroll
        for (int i = 0; i < 2; i++) {
            #pragma unroll
            for (int j = 0; j < 4; j++) {
                int rl0 = wm + i*16 + r;
                int cl0 = wnS + j*8 + c*2;
                int grow0 = qt*FBM + rl0, gcol0 = kb*FBN + cl0;
                float* t = sacc[i*4+j];
                sS[rl0*SSTR + cl0]       = (gcol0   <= grow0  ) ? t[0]*scale : -1e30f;
                sS[rl0*SSTR + cl0+1]     = (gcol0+1 <= grow0  ) ? t[1]*scale : -1e30f;
                sS[(rl0+8)*SSTR + cl0]   = (gcol0   <= grow0+8) ? t[2]*scale : -1e30f;
                sS[(rl0+8)*SSTR + cl0+1] = (gcol0+1 <= grow0+8) ? t[3]*scale : -1e30f;
            }
        }
        __syncthreads();

        // ---- online softmax: 2 threads per row ----
        {
            int row = tid >> 1, part = tid & 1;
            float mo = sMx[row];
            float mx = mo;
            #pragma unroll
            for (int jj = 0; jj < 32; jj++)
                mx = fmaxf(mx, sS[row*SSTR + part*32 + jj]);
            mx = fmaxf(mx, __shfl_xor_sync(0xffffffffu, mx, 1));
            float sum = 0.f;
            #pragma unroll
            for (int jj = 0; jj < 32; jj++) {
                float p = to_tf32(__expf(sS[row*SSTR + part*32 + jj] - mx));
                sS[row*SSTR + part*32 + jj] = p;
                sum += p;
            }
            sum += __shfl_xor_sync(0xffffffffu, sum, 1);
            if (part == 0) {
                float al = __expf(mo - mx);
                sL[row] = sL[row]*al + sum;
                sMx[row] = mx;
                sA[row] = al;
            }
        }
        __syncthreads();

        // ---- O = O*alpha + P V : warp tile 32x64 (2 m-tiles x 8 n-tiles) ----
        #pragma unroll
        for (int i = 0; i < 2; i++) {
            float al0 = sA[wm + i*16 + r];
            float al1 = sA[wm + i*16 + r + 8];
            #pragma unroll
            for (int j = 0; j < 8; j++) {
                oacc[i*8+j][0] *= al0; oacc[i*8+j][1] *= al0;
                oacc[i*8+j][2] *= al1; oacc[i*8+j][3] *= al1;
            }
        }
        #pragma unroll
        for (int s = 0; s < 8; s++) {
            int kc = s * 8;
            uint32_t af[2][4], bf[8][2];
            #pragma unroll
            for (int i = 0; i < 2; i++) {
                int m0 = wm + i*16 + r;
                af[i][0] = __float_as_uint(sS[m0*SSTR      + kc+c]);
                af[i][1] = __float_as_uint(sS[(m0+8)*SSTR  + kc+c]);
                af[i][2] = __float_as_uint(sS[m0*SSTR      + kc+c+4]);
                af[i][3] = __float_as_uint(sS[(m0+8)*SSTR  + kc+c+4]);
            }
            int vr0 = (kc + c) * DH, vr1 = (kc + c + 4) * DH;
            #pragma unroll
            for (int j = 0; j < 8; j++) {
                bf[j][0] = __float_as_uint(Vb[vr0 + vcol0[j]]);
                bf[j][1] = __float_as_uint(Vb[vr1 + vcol1[j]]);
            }
            #pragma unroll
            for (int i = 0; i < 2; i++)
                #pragma unroll
                for (int j = 0; j < 8; j++)
                    mma_tf32(oacc[i*8+j], af[i][0],af[i][1],af[i][2],af[i][3],
                             bf[j][0], bf[j][1]);
        }
    }
    __syncthreads();

    // epilogue: O /= L, tf32-round (feeds WO GEMM), write
    #pragma unroll
    for (int i = 0; i < 2; i++) {
        int rl0 = wm + i*16 + r;
        float inv0 = 1.0f / sL[rl0];
        float inv1 = 1.0f / sL[rl0 + 8];
        int q0 = qt*FBM + rl0;
        #pragma unroll
        for (int j = 0; j < 8; j++) {
            int col = wnO + j*8 + c*2;
            float2 v0, v1;
            v0.x = to_tf32(oacc[i*8+j][0]*inv0); v0.y = to_tf32(oacc[i*8+j][1]*inv0);
            v1.x = to_tf32(oacc[i*8+j][2]*inv1); v1.y = to_tf32(oacc[i*8+j][3]*inv1);
            *(float2*)&g_attn[((size_t)(b*QLEN + q0  ))*(HQ*DH) + h*DH + col] = v0;
            *(float2*)&g_attn[((size_t)(b*QLEN + q0+8))*(HQ*DH) + h*DH + col] = v1;
        }
    }
}

// ---------------------------------------------------------------------------
extern "C" void kernel_launch(void* const* d_in, const int* in_sizes, int n_in,
                              void* d_out, int out_size)
{
    const int*   positions = (const int*)  d_in[0];
    const float* hidden    = (const float*)d_in[1];
    const float* wqkv      = (const float*)d_in[4];
    const float* wo        = (const float*)d_in[5];
    const float* qw        = (const float*)d_in[6];
    const float* kw        = (const float*)d_in[7];
    float* out = (float*)d_out;

    float *p_qkv, *p_attn, *p_hidr, *p_wqkvr, *p_wor;
    cudaGetSymbolAddress((void**)&p_qkv,   g_qkv);
    cudaGetSymbolAddress((void**)&p_attn,  g_attn);
    cudaGetSymbolAddress((void**)&p_hidr,  g_hidr);
    cudaGetSymbolAddress((void**)&p_wqkvr, g_wqkvr);
    cudaGetSymbolAddress((void**)&p_wor,   g_wor);

    cudaFuncSetAttribute(gemm_tf32,  cudaFuncAttributeMaxDynamicSharedMemorySize, GEMM_SMEM);
    cudaFuncSetAttribute(flash_attn, cudaFuncAttributeMaxDynamicSharedMemorySize, FLASH_SMEM);

    // 0) tf32 rounding prepass (RNA)
    round_tf32_vec<<<(NTOK*HID/4 + 255)/256, 256>>>(hidden, p_hidr, NTOK*HID/4);
    round_tf32_vec<<<(QKVN*HID/4 + 255)/256, 256>>>(wqkv, p_wqkvr, QKVN*HID/4);
    round_tf32_vec<<<(HID*HID/4 + 255)/256, 256>>>(wo, p_wor, HID*HID/4);

    // 1) QKV projection
    gemm_tf32<<<dim3(QKVN/128, NTOK/128), 256, GEMM_SMEM>>>(p_hidr, p_wqkvr, p_qkv, NTOK, QKVN, HID);

    // 2) RMSNorm + RoPE + scatter
    rmsnorm_rope<<<dim3(NTOK, 24), 128>>>(positions, qw, kw);

    // 3) causal GQA flash attention (Q tile 128, longest-first)
    flash_attn<<<dim3(QLEN/FBM, HQ, B_), 256, FLASH_SMEM>>>();

    // 4) output projection
    gemm_tf32<<<dim3(HID/128, NTOK/128), 256, GEMM_SMEM>>>(p_attn, p_wor, out, NTOK, HID, HID);
}